// round 1
// baseline (speedup 1.0000x reference)
#include <cuda_runtime.h>
#include <math.h>

// Problem constants (fixed by the dataset reference)
constexpr int B  = 4;
constexpr int N  = 10;
constexpr int K  = 5;
constexpr int Q  = 512;
constexpr int D  = 1536;          // 2 * HID
constexpr int T1 = D / 4;         // 384 float4 lanes
constexpr int QC = 32;            // query chunks
constexpr int QPC = Q / QC;       // 16 query rows per chunk

// Scratch (allocation-free: __device__ globals)
__device__ float4 g_psum[QC * B * T1];    // per-chunk per-dim column sums
__device__ float  g_psumsq[QC * B * T1];  // per-chunk per-lane sum of squares

// ---------------------------------------------------------------------------
// Kernel 1: partial reduction over queries.
// grid = (B, QC), block = 384 threads (one float4 lane each).
// Each block sums QPC=16 query rows: coalesced float4 loads.
// ---------------------------------------------------------------------------
__global__ __launch_bounds__(T1) void qreduce_kernel(const float* __restrict__ query)
{
    const int t  = threadIdx.x;
    const int b  = blockIdx.x;
    const int qc = blockIdx.y;

    const float4* qp = reinterpret_cast<const float4*>(query)
                     + (size_t)b * Q * T1 + (size_t)qc * QPC * T1 + t;

    float4 s  = make_float4(0.f, 0.f, 0.f, 0.f);
    float  s2 = 0.f;
    #pragma unroll
    for (int i = 0; i < QPC; ++i) {
        float4 v = qp[(size_t)i * T1];
        s.x += v.x; s.y += v.y; s.z += v.z; s.w += v.w;
        s2  += v.x * v.x + v.y * v.y + v.z * v.z + v.w * v.w;
    }
    const int idx = (qc * B + b) * T1 + t;
    g_psum[idx]   = s;
    g_psumsq[idx] = s2;
}

// ---------------------------------------------------------------------------
// Kernel 2: per-(b,n) class block.
// 1. Reduce the QC partials -> x_bar (float4 per lane) + csum partial.
// 2. For each k: dot(s_k, x_bar), ||s_k||^2 with support held in registers.
// 3. Block-reduce 11 scalars, thread 0 does tanh + softmax over K,
//    writes qgw, broadcasts weights via shared memory.
// 4. All lanes write agg = sum_k w_k * s_k from registers.
// ---------------------------------------------------------------------------
__global__ __launch_bounds__(T1) void proto_kernel(const float* __restrict__ support,
                                                   float* __restrict__ out)
{
    const int t = threadIdx.x;
    const int b = blockIdx.x / N;
    const int n = blockIdx.x % N;

    constexpr float invQ = 1.0f / (float)Q;

    // --- reduce query partials ---
    float4 xb = make_float4(0.f, 0.f, 0.f, 0.f);
    float  cs = 0.f;
    #pragma unroll
    for (int qc = 0; qc < QC; ++qc) {
        const int idx = (qc * B + b) * T1 + t;
        float4 v = g_psum[idx];
        xb.x += v.x; xb.y += v.y; xb.z += v.z; xb.w += v.w;
        cs   += g_psumsq[idx];
    }
    xb.x *= invQ; xb.y *= invQ; xb.z *= invQ; xb.w *= invQ;

    // --- support dots/norms, support cached in registers ---
    float4 s4[K];
    float  vals[2 * K + 1];   // dot[0..K), snorm[K..2K), csum at [2K]
    const float4* sp = reinterpret_cast<const float4*>(support)
                     + ((size_t)(b * N + n) * K) * T1 + t;
    #pragma unroll
    for (int k = 0; k < K; ++k) {
        float4 v = sp[(size_t)k * T1];
        s4[k] = v;
        vals[k]     = v.x * xb.x + v.y * xb.y + v.z * xb.z + v.w * xb.w;
        vals[K + k] = v.x * v.x + v.y * v.y + v.z * v.z + v.w * v.w;
    }
    vals[2 * K] = cs;

    // --- block reduction of 11 scalars (12 warps) ---
    constexpr int NW = T1 / 32;
    __shared__ float red[NW][2 * K + 1];
    const int wid = t >> 5, lid = t & 31;
    #pragma unroll
    for (int j = 0; j < 2 * K + 1; ++j) {
        float v = vals[j];
        #pragma unroll
        for (int off = 16; off > 0; off >>= 1)
            v += __shfl_xor_sync(0xFFFFFFFFu, v, off);
        if (lid == 0) red[wid][j] = v;
    }
    __syncthreads();

    __shared__ float wsh[K];
    if (t == 0) {
        float tot[2 * K + 1];
        #pragma unroll
        for (int j = 0; j < 2 * K + 1; ++j) {
            float a = 0.f;
            #pragma unroll
            for (int w2 = 0; w2 < NW; ++w2) a += red[w2][j];
            tot[j] = a;
        }
        const float c = tot[2 * K] * invQ;  // mean_q ||x_q||^2
        float tk[K], mx = -1e30f;
        #pragma unroll
        for (int k = 0; k < K; ++k) {
            // mean_q -||s - x_q||^2 = -(||s||^2 - 2 s.xbar + c)
            const float m = -(tot[K + k] - 2.0f * tot[k] + c);
            tk[k] = tanhf(m);
            mx = fmaxf(mx, tk[k]);
        }
        float sum = 0.f, e[K];
        #pragma unroll
        for (int k = 0; k < K; ++k) { e[k] = expf(tk[k] - mx); sum += e[k]; }
        const float inv = 1.0f / sum;
        #pragma unroll
        for (int k = 0; k < K; ++k) {
            const float w = e[k] * inv;
            wsh[k] = w;
            out[(size_t)B * N * D + (size_t)(b * N + n) * K + k] = w;  // qgw
        }
    }
    __syncthreads();

    // --- weighted aggregation from registers ---
    float4 a = make_float4(0.f, 0.f, 0.f, 0.f);
    #pragma unroll
    for (int k = 0; k < K; ++k) {
        const float w = wsh[k];
        a.x += s4[k].x * w; a.y += s4[k].y * w;
        a.z += s4[k].z * w; a.w += s4[k].w * w;
    }
    reinterpret_cast<float4*>(out)[(size_t)(b * N + n) * T1 + t] = a;
}

extern "C" void kernel_launch(void* const* d_in, const int* in_sizes, int n_in,
                              void* d_out, int out_size)
{
    const float* support = (const float*)d_in[0];  // (B, N, K, D)
    const float* query   = (const float*)d_in[1];  // (B, Q, D)
    float* out = (float*)d_out;                    // agg (B,N,D) then qgw (B,N,K,1)

    dim3 g1(B, QC);
    qreduce_kernel<<<g1, T1>>>(query);
    proto_kernel<<<B * N, T1>>>(support, out);
}

// round 2
// speedup vs baseline: 1.0029x; 1.0029x over previous
#include <cuda_runtime.h>
#include <math.h>

// Problem constants (fixed by the dataset reference)
constexpr int B   = 4;
constexpr int N   = 10;
constexpr int K   = 5;
constexpr int Q   = 512;
constexpr int D   = 1536;         // 2 * HID
constexpr int T1  = D / 4;        // 384 float4 lanes per row
constexpr int QC  = 32;           // query chunks per batch
constexpr int QPC = Q / QC;       // 16 rows per chunk
constexpr int GRID   = B * QC;    // 128 blocks (all co-resident on 148 SMs)
constexpr int NTHR   = 768;       // 2 "halves" of 384 lanes
constexpr int HALFQ  = QPC / 2;   // 8 rows per thread in phase 1

// Scratch (allocation-free: __device__ globals)
__device__ float4 g_psum[QC * B * T1];
__device__ float  g_psumsq[QC * B * T1];
__device__ unsigned int g_ticket;   // monotonic across graph replays

__device__ __forceinline__ float4 f4add(float4 a, float4 b) {
    return make_float4(a.x + b.x, a.y + b.y, a.z + b.z, a.w + b.w);
}

__global__ __launch_bounds__(NTHR, 1)
void fused_proto_kernel(const float* __restrict__ support,
                        const float* __restrict__ query,
                        float* __restrict__ out)
{
    const int t    = threadIdx.x;
    const int half = t / T1;          // 0 or 1
    const int lane = t - half * T1;   // 0..383

    __shared__ float4 shp[NTHR];
    __shared__ float  shp2[NTHR];
    __shared__ float  red[T1 / 32][2 * K + 1];
    __shared__ float  wsh[K];

    constexpr float invQ = 1.0f / (float)Q;

    // ======================= Phase 1: query reduction =======================
    {
        const int b  = blockIdx.x >> 5;     // /QC
        const int qc = blockIdx.x & 31;     // %QC

        const float4* qp = reinterpret_cast<const float4*>(query)
                         + (size_t)b * Q * T1
                         + (size_t)(qc * QPC + half * HALFQ) * T1 + lane;

        float4 s  = make_float4(0.f, 0.f, 0.f, 0.f);
        float  s2 = 0.f;
        #pragma unroll
        for (int i = 0; i < HALFQ; ++i) {
            float4 v = qp[(size_t)i * T1];
            s.x += v.x; s.y += v.y; s.z += v.z; s.w += v.w;
            s2  += v.x * v.x + v.y * v.y + v.z * v.z + v.w * v.w;
        }
        shp[t] = s; shp2[t] = s2;
        __syncthreads();
        if (half == 0) {
            const int idx = (qc * B + b) * T1 + lane;
            g_psum[idx]   = f4add(s, shp[t + T1]);
            g_psumsq[idx] = s2 + shp2[t + T1];
        }
        __threadfence();
        __syncthreads();
    }

    // ====================== Grid barrier (ticket spin) ======================
    {
        if (t == 0) {
            unsigned my = atomicAdd(&g_ticket, 1u) + 1u;
            unsigned target = ((my + (unsigned)GRID - 1u) / (unsigned)GRID) * (unsigned)GRID;
            for (;;) {
                unsigned v;
                asm volatile("ld.acquire.gpu.u32 %0, [%1];" : "=r"(v) : "l"(&g_ticket));
                if (v >= target) break;
                __nanosleep(64);
            }
        }
        __syncthreads();
    }

    // ================== Phase 2: per-(b,n) class blocks =====================
    if (blockIdx.x >= B * N) return;
    const int b = blockIdx.x / N;
    const int n = blockIdx.x % N;

    // Split the 32-chunk partial reduce across both halves (16 chunks each).
    float4 p  = make_float4(0.f, 0.f, 0.f, 0.f);
    float  p2 = 0.f;
    #pragma unroll
    for (int j = 0; j < QC / 2; ++j) {
        const int qc  = half * (QC / 2) + j;
        const int idx = (qc * B + b) * T1 + lane;
        float4 v = g_psum[idx];
        p.x += v.x; p.y += v.y; p.z += v.z; p.w += v.w;
        p2  += g_psumsq[idx];
    }
    shp[t] = p; shp2[t] = p2;
    __syncthreads();

    float4 s4[K];
    if (half == 0) {
        float4 o = shp[t + T1];
        float4 xb = make_float4((p.x + o.x) * invQ, (p.y + o.y) * invQ,
                                (p.z + o.z) * invQ, (p.w + o.w) * invQ);
        const float cs = p2 + shp2[t + T1];

        float vals[2 * K + 1];
        const float4* sp = reinterpret_cast<const float4*>(support)
                         + ((size_t)(b * N + n) * K) * T1 + lane;
        #pragma unroll
        for (int k = 0; k < K; ++k) {
            float4 v = sp[(size_t)k * T1];
            s4[k] = v;
            vals[k]     = v.x * xb.x + v.y * xb.y + v.z * xb.z + v.w * xb.w;
            vals[K + k] = v.x * v.x + v.y * v.y + v.z * v.z + v.w * v.w;
        }
        vals[2 * K] = cs;

        const int wid = lane >> 5, lid = lane & 31;
        #pragma unroll
        for (int j = 0; j < 2 * K + 1; ++j) {
            float v = vals[j];
            #pragma unroll
            for (int off = 16; off > 0; off >>= 1)
                v += __shfl_xor_sync(0xFFFFFFFFu, v, off);
            if (lid == 0) red[wid][j] = v;
        }
    }
    __syncthreads();

    if (t == 0) {
        float tot[2 * K + 1];
        #pragma unroll
        for (int j = 0; j < 2 * K + 1; ++j) {
            float a = 0.f;
            #pragma unroll
            for (int w2 = 0; w2 < T1 / 32; ++w2) a += red[w2][j];
            tot[j] = a;
        }
        const float c = tot[2 * K] * invQ;   // mean_q ||x_q||^2
        float tk[K], mx = -1e30f;
        #pragma unroll
        for (int k = 0; k < K; ++k) {
            const float m = -(tot[K + k] - 2.0f * tot[k] + c);
            tk[k] = tanhf(m);
            mx = fmaxf(mx, tk[k]);
        }
        float sum = 0.f, e[K];
        #pragma unroll
        for (int k = 0; k < K; ++k) { e[k] = expf(tk[k] - mx); sum += e[k]; }
        const float inv = 1.0f / sum;
        #pragma unroll
        for (int k = 0; k < K; ++k) {
            const float w = e[k] * inv;
            wsh[k] = w;
            out[(size_t)B * N * D + (size_t)(b * N + n) * K + k] = w;   // qgw
        }
    }
    __syncthreads();

    if (half == 0) {
        float4 a = make_float4(0.f, 0.f, 0.f, 0.f);
        #pragma unroll
        for (int k = 0; k < K; ++k) {
            const float w = wsh[k];
            a.x += s4[k].x * w; a.y += s4[k].y * w;
            a.z += s4[k].z * w; a.w += s4[k].w * w;
        }
        reinterpret_cast<float4*>(out)[(size_t)(b * N + n) * T1 + lane] = a;
    }
}

extern "C" void kernel_launch(void* const* d_in, const int* in_sizes, int n_in,
                              void* d_out, int out_size)
{
    const float* support = (const float*)d_in[0];  // (B, N, K, D)
    const float* query   = (const float*)d_in[1];  // (B, Q, D)
    float* out = (float*)d_out;                    // agg (B,N,D) then qgw (B,N,K,1)

    fused_proto_kernel<<<GRID, NTHR>>>(support, query, out);
}